// round 5
// baseline (speedup 1.0000x reference)
#include <cuda_runtime.h>

#define D          128
#define DV         (D / 4)      // 32 float4 per row
#define NWARPS     8
#define NTHREADS   256
#define SMEM_ROWS  96           // rows cached in smem (48KB dynamic)
#define REG_J      4            // float4 rows per thread in registers
#define CACHED     (SMEM_ROWS + REG_J * NWARPS)   // 128 rows total cached
#define SMEM_BYTES (SMEM_ROWS * 64 * 8)           // 96*512 = 49152
#define MAXB       16384
#define TR         32           // GEMM row tile

// Scratch (allocation-free per harness rules)
__device__ int   g_seg_start[MAXB + 1];
__device__ float g_pooled[(size_t)MAXB * D];

// ---- L2 eviction-policy hinted float4 loads (createpolicy + cache_hint) ----
__device__ __forceinline__ unsigned long long mk_policy_evict_last() {
    unsigned long long p;
    asm("createpolicy.fractional.L2::evict_last.b64 %0, 1.0;" : "=l"(p));
    return p;
}
__device__ __forceinline__ unsigned long long mk_policy_evict_first() {
    unsigned long long p;
    asm("createpolicy.fractional.L2::evict_first.b64 %0, 1.0;" : "=l"(p));
    return p;
}
__device__ __forceinline__ float4 ldg_hint(const float4* p, unsigned long long pol) {
    float4 v;
    asm volatile("ld.global.nc.L2::cache_hint.v4.f32 {%0,%1,%2,%3}, [%4], %5;"
                 : "=f"(v.x), "=f"(v.y), "=f"(v.z), "=f"(v.w)
                 : "l"(p), "l"(pol));
    return v;
}

// ---------------------------------------------------------------------------
// Kernel 0: segment boundaries, vectorized adjacent-diff scan.
// ---------------------------------------------------------------------------
__global__ void seg_bounds_scan(const int4* __restrict__ batch4,
                                const int*  __restrict__ batch, int N, int B)
{
    int t  = blockIdx.x * blockDim.x + threadIdx.x;
    int i  = t * 4;
    int nt = (N + 3) / 4;
    if (t > nt) return;
    if (t == nt) {
        int last = batch[N - 1];
        for (int v = last + 1; v <= B; v++) g_seg_start[v] = N;
        return;
    }
    int prev = (i == 0) ? -1 : batch[i - 1];
    if (i + 3 < N) {
        int4 c = batch4[t];
        int vals[4] = {c.x, c.y, c.z, c.w};
#pragma unroll
        for (int k = 0; k < 4; k++) {
            for (int v = prev + 1; v <= vals[k]; v++) g_seg_start[v] = i + k;
            prev = vals[k];
        }
    } else {
        for (int k = 0; k < 4 && i + k < N; k++) {
            int cur = batch[i + k];
            for (int v = prev + 1; v <= cur; v++) g_seg_start[v] = i + k;
            prev = cur;
        }
    }
}

// ---------------------------------------------------------------------------
// Kernel 1: per-segment attention pooling. One CTA per segment.
// 4 CTAs/SM (52.6KB smem, <=64 regs). Cache = 96 smem rows + 32 reg rows.
// Warp w owns rows r = start + w + 8j  (cache index c = w + 8j):
//   j in [0,12)   -> smem cache   (c in [0,96))
//   j in [12,16)  -> reg cache    (c in [96,128)), static index j-12
//   j >= 16       -> uncached: pass1 load evict_last, pass2 load evict_first
// Cached-row pass1 loads use evict_first (never re-read from memory).
// ---------------------------------------------------------------------------
__global__ void __launch_bounds__(NTHREADS, 4)
attention_pool_kernel(const float4* __restrict__ x)
{
    extern __shared__ float4 s_cache[];          // SMEM_ROWS * DV
    __shared__ float4 s_partial[NWARPS][DV];     // 4KB
    __shared__ float4 s_coarse[DV];              // 512B

    const int b     = blockIdx.x;
    const int start = g_seg_start[b];
    const int end   = g_seg_start[b + 1];
    const int cnt   = end - start;
    const float inv = 1.0f / (float)(cnt > 0 ? cnt : 1);
    const int w     = threadIdx.x >> 5;
    const int lane  = threadIdx.x & 31;

    const unsigned long long pol_last  = mk_policy_evict_last();
    const unsigned long long pol_first = mk_policy_evict_first();

    float4 vc[REG_J];                            // register row cache

    // ---- Pass 1: column sums ----
    float4 s = make_float4(0.f, 0.f, 0.f, 0.f);

#pragma unroll
    for (int j = 0; j < 12; j++) {               // smem-cached rows
        int r = start + w + 8 * j;
        if (r < end) {
            float4 v = ldg_hint(&x[(size_t)r * DV + lane], pol_first);
            s_cache[(w + 8 * j) * DV + lane] = v;
            s.x += v.x; s.y += v.y; s.z += v.z; s.w += v.w;
        }
    }
#pragma unroll
    for (int jj = 0; jj < REG_J; jj++) {         // reg-cached rows
        int r = start + w + 8 * (12 + jj);
        vc[jj] = make_float4(0.f, 0.f, 0.f, 0.f);
        if (r < end) {
            float4 v = ldg_hint(&x[(size_t)r * DV + lane], pol_first);
            vc[jj] = v;
            s.x += v.x; s.y += v.y; s.z += v.z; s.w += v.w;
        }
    }
    {
        int r = start + w + 8 * (12 + REG_J);
        for (; r + NWARPS < end; r += 2 * NWARPS) {
            float4 v0 = ldg_hint(&x[(size_t)r * DV + lane], pol_last);
            float4 v1 = ldg_hint(&x[(size_t)(r + NWARPS) * DV + lane], pol_last);
            s.x += v0.x + v1.x; s.y += v0.y + v1.y;
            s.z += v0.z + v1.z; s.w += v0.w + v1.w;
        }
        if (r < end) {
            float4 v = ldg_hint(&x[(size_t)r * DV + lane], pol_last);
            s.x += v.x; s.y += v.y; s.z += v.z; s.w += v.w;
        }
    }
    s_partial[w][lane] = s;
    __syncthreads();
    if (threadIdx.x < 32) {
        float4 c = s_partial[0][lane];
#pragma unroll
        for (int i = 1; i < NWARPS; i++) {
            float4 t = s_partial[i][lane];
            c.x += t.x; c.y += t.y; c.z += t.z; c.w += t.w;
        }
        c.x *= inv; c.y *= inv; c.z *= inv; c.w *= inv;
        s_coarse[lane] = c;
    }
    __syncthreads();
    const float4 cf = s_coarse[lane];

    // ---- Pass 2: att + scaled accumulation ----
    float4 acc = make_float4(0.f, 0.f, 0.f, 0.f);

#pragma unroll
    for (int j = 0; j < 12; j++) {               // from smem
        int r = start + w + 8 * j;
        if (r < end) {
            float4 v = s_cache[(w + 8 * j) * DV + lane];
            float d = v.x * cf.x + v.y * cf.y + v.z * cf.z + v.w * cf.w;
#pragma unroll
            for (int o = 16; o > 0; o >>= 1)
                d += __shfl_xor_sync(0xffffffffu, d, o);
            acc.x += v.x * d; acc.y += v.y * d;
            acc.z += v.z * d; acc.w += v.w * d;
        }
    }
#pragma unroll
    for (int jj = 0; jj < REG_J; jj++) {         // from registers
        int r = start + w + 8 * (12 + jj);
        if (r < end) {
            float4 v = vc[jj];
            float d = v.x * cf.x + v.y * cf.y + v.z * cf.z + v.w * cf.w;
#pragma unroll
            for (int o = 16; o > 0; o >>= 1)
                d += __shfl_xor_sync(0xffffffffu, d, o);
            acc.x += v.x * d; acc.y += v.y * d;
            acc.z += v.z * d; acc.w += v.w * d;
        }
    }
    {
        int r = start + w + 8 * (12 + REG_J);
        for (; r + NWARPS < end; r += 2 * NWARPS) {
            float4 v0 = ldg_hint(&x[(size_t)r * DV + lane], pol_first);
            float4 v1 = ldg_hint(&x[(size_t)(r + NWARPS) * DV + lane], pol_first);
            float d0 = v0.x * cf.x + v0.y * cf.y + v0.z * cf.z + v0.w * cf.w;
            float d1 = v1.x * cf.x + v1.y * cf.y + v1.z * cf.z + v1.w * cf.w;
#pragma unroll
            for (int o = 16; o > 0; o >>= 1) {
                d0 += __shfl_xor_sync(0xffffffffu, d0, o);
                d1 += __shfl_xor_sync(0xffffffffu, d1, o);
            }
            acc.x += v0.x * d0 + v1.x * d1;
            acc.y += v0.y * d0 + v1.y * d1;
            acc.z += v0.z * d0 + v1.z * d1;
            acc.w += v0.w * d0 + v1.w * d1;
        }
        if (r < end) {
            float4 v = ldg_hint(&x[(size_t)r * DV + lane], pol_first);
            float d = v.x * cf.x + v.y * cf.y + v.z * cf.z + v.w * cf.w;
#pragma unroll
            for (int o = 16; o > 0; o >>= 1)
                d += __shfl_xor_sync(0xffffffffu, d, o);
            acc.x += v.x * d; acc.y += v.y * d;
            acc.z += v.z * d; acc.w += v.w * d;
        }
    }
    s_partial[w][lane] = acc;
    __syncthreads();
    if (threadIdx.x < 32) {
        float4 p = s_partial[0][lane];
#pragma unroll
        for (int i = 1; i < NWARPS; i++) {
            float4 t = s_partial[i][lane];
            p.x += t.x; p.y += t.y; p.z += t.z; p.w += t.w;
        }
        p.x *= inv; p.y *= inv; p.z *= inv; p.w *= inv;
        ((float4*)g_pooled)[(size_t)b * DV + lane] = p;
    }
}

// ---------------------------------------------------------------------------
// Kernel 2: out[B,128] = pooled[B,128] @ W^T + bias.
// ---------------------------------------------------------------------------
__global__ void __launch_bounds__(128)
out_gemm_kernel(const float* __restrict__ W, const float* __restrict__ bias,
                float* __restrict__ out, int B)
{
    __shared__ float sp[TR][D];   // 16KB
    const int rb = blockIdx.x * TR;
    int rows = B - rb; if (rows > TR) rows = TR;

    const float4* src = (const float4*)(g_pooled + (size_t)rb * D);
    float4* dst = (float4*)sp;
    for (int i = threadIdx.x; i < rows * DV; i += 128) dst[i] = src[i];
    __syncthreads();

    const int j = threadIdx.x;
    float acc[TR];
    const float bj = bias[j];
#pragma unroll
    for (int r2 = 0; r2 < TR; r2++) acc[r2] = bj;

    const float4* W4  = (const float4*)(W + (size_t)j * D);
    const float4* sp4 = (const float4*)sp;
    for (int k = 0; k < DV; k++) {
        float4 wv = W4[k];
#pragma unroll
        for (int r2 = 0; r2 < TR; r2++) {
            float4 pv = sp4[r2 * DV + k];
            acc[r2] += pv.x * wv.x + pv.y * wv.y + pv.z * wv.z + pv.w * wv.w;
        }
    }
    for (int r2 = 0; r2 < rows; r2++)
        out[(size_t)(rb + r2) * D + j] = acc[r2];
}

// ---------------------------------------------------------------------------
extern "C" void kernel_launch(void* const* d_in, const int* in_sizes, int n_in,
                              void* d_out, int out_size)
{
    const float* x     = (const float*)d_in[0];
    const int*   batch = (const int*)  d_in[1];
    const float* W     = (const float*)d_in[2];
    const float* bias  = (const float*)d_in[3];
    (void)n_in;

    const int N = in_sizes[1];
    const int B = out_size / D;

    static bool attr_done = false;
    if (!attr_done) {
        cudaFuncSetAttribute(attention_pool_kernel,
                             cudaFuncAttributeMaxDynamicSharedMemorySize,
                             SMEM_BYTES);
        attr_done = true;
    }

    int nt = (N + 3) / 4 + 1;
    seg_bounds_scan<<<(nt + 255) / 256, 256>>>((const int4*)batch, batch, N, B);
    attention_pool_kernel<<<B, NTHREADS, SMEM_BYTES>>>((const float4*)x);
    out_gemm_kernel<<<(B + TR - 1) / TR, 128>>>(W, bias, (float*)d_out, B);
}

// round 6
// speedup vs baseline: 1.0944x; 1.0944x over previous
#include <cuda_runtime.h>

#define D          128
#define DV         (D / 4)      // 32 float4 per row
#define NWARPS     8
#define NTHREADS   256
#define CACHE_ROWS 80           // 80 rows * 512B = 40KB static smem cache
#define MAXB       16384
#define TR         32           // GEMM row tile

// Scratch (allocation-free per harness rules)
__device__ int   g_seg_start[MAXB + 1];
__device__ float g_pooled[(size_t)MAXB * D];

// ---- L2 eviction-policy hinted float4 loads (createpolicy + cache_hint) ----
__device__ __forceinline__ unsigned long long mk_policy_evict_last() {
    unsigned long long p;
    asm("createpolicy.fractional.L2::evict_last.b64 %0, 1.0;" : "=l"(p));
    return p;
}
__device__ __forceinline__ unsigned long long mk_policy_evict_first() {
    unsigned long long p;
    asm("createpolicy.fractional.L2::evict_first.b64 %0, 1.0;" : "=l"(p));
    return p;
}
__device__ __forceinline__ float4 ldg_hint(const float4* p, unsigned long long pol) {
    float4 v;
    asm volatile("ld.global.nc.L2::cache_hint.v4.f32 {%0,%1,%2,%3}, [%4], %5;"
                 : "=f"(v.x), "=f"(v.y), "=f"(v.z), "=f"(v.w)
                 : "l"(p), "l"(pol));
    return v;
}

// ---------------------------------------------------------------------------
// Kernel 0: segment boundaries, vectorized adjacent-diff scan.
// ---------------------------------------------------------------------------
__global__ void seg_bounds_scan(const int4* __restrict__ batch4,
                                const int*  __restrict__ batch, int N, int B)
{
    int t  = blockIdx.x * blockDim.x + threadIdx.x;
    int i  = t * 4;
    int nt = (N + 3) / 4;
    if (t > nt) return;
    if (t == nt) {
        int last = batch[N - 1];
        for (int v = last + 1; v <= B; v++) g_seg_start[v] = N;
        return;
    }
    int prev = (i == 0) ? -1 : batch[i - 1];
    if (i + 3 < N) {
        int4 c = batch4[t];
        int vals[4] = {c.x, c.y, c.z, c.w};
#pragma unroll
        for (int k = 0; k < 4; k++) {
            for (int v = prev + 1; v <= vals[k]; v++) g_seg_start[v] = i + k;
            prev = vals[k];
        }
    } else {
        for (int k = 0; k < 4 && i + k < N; k++) {
            int cur = batch[i + k];
            for (int v = prev + 1; v <= cur; v++) g_seg_start[v] = i + k;
            prev = cur;
        }
    }
}

// ---------------------------------------------------------------------------
// Kernel 1: per-segment attention pooling. One CTA per segment.
// R4 config: 40KB static cache -> 5 CTAs/SM, ~740 concurrent segments.
// Pass 1 (ascending): column sums -> coarse. First 80 rows -> smem (loaded
//   evict_first: never re-read from gmem). Uncached rows loaded evict_last.
// Pass 2 (LIFO): uncached rows walked in REVERSE order (newest first) so
//   re-reads hit L2 (stack reuse == LRU), with evict_first (dead after use);
//   then cached rows from smem.
// ---------------------------------------------------------------------------
__global__ void __launch_bounds__(NTHREADS)
attention_pool_kernel(const float4* __restrict__ x)
{
    __shared__ float4 s_partial[NWARPS][DV];     // 4KB
    __shared__ float4 s_coarse[DV];              // 512B
    __shared__ float4 s_cache[CACHE_ROWS * DV];  // 40KB

    const int b     = blockIdx.x;
    const int start = g_seg_start[b];
    const int end   = g_seg_start[b + 1];
    const int cnt   = end - start;
    const float inv = 1.0f / (float)(cnt > 0 ? cnt : 1);
    const int w     = threadIdx.x >> 5;
    const int lane  = threadIdx.x & 31;

    const unsigned long long pol_last  = mk_policy_evict_last();
    const unsigned long long pol_first = mk_policy_evict_first();

    // ---- Pass 1: column sums (ascending) ----
    float4 s = make_float4(0.f, 0.f, 0.f, 0.f);
    int r = start + w;
    for (; r + 3 * NWARPS < end; r += 4 * NWARPS) {
        float4 v[4];
#pragma unroll
        for (int k = 0; k < 4; k++) {
            int c = (r - start) + k * NWARPS;
            const float4* p = &x[(size_t)(r + k * NWARPS) * DV + lane];
            v[k] = ldg_hint(p, (c < CACHE_ROWS) ? pol_first : pol_last);
        }
#pragma unroll
        for (int k = 0; k < 4; k++) {
            int c = (r - start) + k * NWARPS;
            if (c < CACHE_ROWS) s_cache[c * DV + lane] = v[k];
            s.x += v[k].x; s.y += v[k].y; s.z += v[k].z; s.w += v[k].w;
        }
    }
    for (; r < end; r += NWARPS) {
        int c = r - start;
        const float4* p = &x[(size_t)r * DV + lane];
        float4 v = ldg_hint(p, (c < CACHE_ROWS) ? pol_first : pol_last);
        if (c < CACHE_ROWS) s_cache[c * DV + lane] = v;
        s.x += v.x; s.y += v.y; s.z += v.z; s.w += v.w;
    }
    s_partial[w][lane] = s;
    __syncthreads();
    if (threadIdx.x < 32) {
        float4 c = s_partial[0][lane];
#pragma unroll
        for (int i = 1; i < NWARPS; i++) {
            float4 t = s_partial[i][lane];
            c.x += t.x; c.y += t.y; c.z += t.z; c.w += t.w;
        }
        c.x *= inv; c.y *= inv; c.z *= inv; c.w *= inv;
        s_coarse[lane] = c;
    }
    __syncthreads();
    const float4 cf = s_coarse[lane];

    // ---- Pass 2a: UNCACHED rows in reverse order (LIFO -> L2 hits) ----
    float4 acc = make_float4(0.f, 0.f, 0.f, 0.f);
    const int ucut = start + CACHE_ROWS;         // first uncached row
    r = end - 1 - w;
    for (; r - NWARPS >= ucut; r -= 2 * NWARPS) {
        float4 v0 = ldg_hint(&x[(size_t)r * DV + lane], pol_first);
        float4 v1 = ldg_hint(&x[(size_t)(r - NWARPS) * DV + lane], pol_first);
        float d0 = v0.x * cf.x + v0.y * cf.y + v0.z * cf.z + v0.w * cf.w;
        float d1 = v1.x * cf.x + v1.y * cf.y + v1.z * cf.z + v1.w * cf.w;
#pragma unroll
        for (int o = 16; o > 0; o >>= 1) {
            d0 += __shfl_xor_sync(0xffffffffu, d0, o);
            d1 += __shfl_xor_sync(0xffffffffu, d1, o);
        }
        acc.x += v0.x * d0 + v1.x * d1;
        acc.y += v0.y * d0 + v1.y * d1;
        acc.z += v0.z * d0 + v1.z * d1;
        acc.w += v0.w * d0 + v1.w * d1;
    }
    if (r >= ucut) {
        float4 v = ldg_hint(&x[(size_t)r * DV + lane], pol_first);
        float d = v.x * cf.x + v.y * cf.y + v.z * cf.z + v.w * cf.w;
#pragma unroll
        for (int o = 16; o > 0; o >>= 1)
            d += __shfl_xor_sync(0xffffffffu, d, o);
        acc.x += v.x * d; acc.y += v.y * d; acc.z += v.z * d; acc.w += v.w * d;
    }

    // ---- Pass 2b: cached rows from smem ----
    {
        const int clim = (cnt < CACHE_ROWS) ? cnt : CACHE_ROWS;
        for (int c0 = w; c0 < clim; c0 += 2 * NWARPS) {
            int c1 = c0 + NWARPS;
            float4 v0 = s_cache[c0 * DV + lane];
            float d0 = v0.x * cf.x + v0.y * cf.y + v0.z * cf.z + v0.w * cf.w;
            float d1 = 0.f;
            float4 v1 = make_float4(0.f, 0.f, 0.f, 0.f);
            if (c1 < clim) {
                v1 = s_cache[c1 * DV + lane];
                d1 = v1.x * cf.x + v1.y * cf.y + v1.z * cf.z + v1.w * cf.w;
            }
#pragma unroll
            for (int o = 16; o > 0; o >>= 1) {
                d0 += __shfl_xor_sync(0xffffffffu, d0, o);
                d1 += __shfl_xor_sync(0xffffffffu, d1, o);
            }
            acc.x += v0.x * d0 + v1.x * d1;
            acc.y += v0.y * d0 + v1.y * d1;
            acc.z += v0.z * d0 + v1.z * d1;
            acc.w += v0.w * d0 + v1.w * d1;
        }
    }

    s_partial[w][lane] = acc;
    __syncthreads();
    if (threadIdx.x < 32) {
        float4 p = s_partial[0][lane];
#pragma unroll
        for (int i = 1; i < NWARPS; i++) {
            float4 t = s_partial[i][lane];
            p.x += t.x; p.y += t.y; p.z += t.z; p.w += t.w;
        }
        p.x *= inv; p.y *= inv; p.z *= inv; p.w *= inv;
        ((float4*)g_pooled)[(size_t)b * DV + lane] = p;
    }
}

// ---------------------------------------------------------------------------
// Kernel 2: out[B,128] = pooled[B,128] @ W^T + bias.
// ---------------------------------------------------------------------------
__global__ void __launch_bounds__(128)
out_gemm_kernel(const float* __restrict__ W, const float* __restrict__ bias,
                float* __restrict__ out, int B)
{
    __shared__ float sp[TR][D];   // 16KB
    const int rb = blockIdx.x * TR;
    int rows = B - rb; if (rows > TR) rows = TR;

    const float4* src = (const float4*)(g_pooled + (size_t)rb * D);
    float4* dst = (float4*)sp;
    for (int i = threadIdx.x; i < rows * DV; i += 128) dst[i] = src[i];
    __syncthreads();

    const int j = threadIdx.x;
    float acc[TR];
    const float bj = bias[j];
#pragma unroll
    for (int r2 = 0; r2 < TR; r2++) acc[r2] = bj;

    const float4* W4  = (const float4*)(W + (size_t)j * D);
    const float4* sp4 = (const float4*)sp;
    for (int k = 0; k < DV; k++) {
        float4 wv = W4[k];
#pragma unroll
        for (int r2 = 0; r2 < TR; r2++) {
            float4 pv = sp4[r2 * DV + k];
            acc[r2] += pv.x * wv.x + pv.y * wv.y + pv.z * wv.z + pv.w * wv.w;
        }
    }
    for (int r2 = 0; r2 < rows; r2++)
        out[(size_t)(rb + r2) * D + j] = acc[r2];
}

// ---------------------------------------------------------------------------
extern "C" void kernel_launch(void* const* d_in, const int* in_sizes, int n_in,
                              void* d_out, int out_size)
{
    const float* x     = (const float*)d_in[0];
    const int*   batch = (const int*)  d_in[1];
    const float* W     = (const float*)d_in[2];
    const float* bias  = (const float*)d_in[3];
    (void)n_in;

    const int N = in_sizes[1];
    const int B = out_size / D;

    int nt = (N + 3) / 4 + 1;
    seg_bounds_scan<<<(nt + 255) / 256, 256>>>((const int4*)batch, batch, N, B);
    attention_pool_kernel<<<B, NTHREADS>>>((const float4*)x);
    out_gemm_kernel<<<(B + TR - 1) / TR, 128>>>(W, bias, (float*)d_out, B);
}

// round 8
// speedup vs baseline: 1.1658x; 1.0652x over previous
#include <cuda_runtime.h>
#include <cstdint>

#define D          128
#define DV         (D / 4)      // 32 float4 per row
#define NWARPS     8
#define NTHREADS   256
#define CACHE_ROWS 160          // bf16 rows: 160 * 256B = 40KB smem cache
#define MAXB       16384
#define TR         32           // GEMM row tile

// Scratch (allocation-free per harness rules)
__device__ int   g_seg_start[MAXB + 1];
__device__ float g_pooled[(size_t)MAXB * D];

// ---- L2 eviction-policy hinted float4 loads ------------------------------
__device__ __forceinline__ unsigned long long mk_policy_evict_last() {
    unsigned long long p;
    asm("createpolicy.fractional.L2::evict_last.b64 %0, 1.0;" : "=l"(p));
    return p;
}
__device__ __forceinline__ unsigned long long mk_policy_evict_first() {
    unsigned long long p;
    asm("createpolicy.fractional.L2::evict_first.b64 %0, 1.0;" : "=l"(p));
    return p;
}
__device__ __forceinline__ float4 ldg_hint(const float4* p, unsigned long long pol) {
    float4 v;
    asm volatile("ld.global.nc.L2::cache_hint.v4.f32 {%0,%1,%2,%3}, [%4], %5;"
                 : "=f"(v.x), "=f"(v.y), "=f"(v.z), "=f"(v.w)
                 : "l"(p), "l"(pol));
    return v;
}

// ---- bf16x2 pack/unpack (unpack is shift/mask — free) ---------------------
__device__ __forceinline__ uint32_t pack_bf16x2(float lo, float hi) {
    uint32_t u;
    asm("cvt.rn.bf16x2.f32 %0, %1, %2;" : "=r"(u) : "f"(hi), "f"(lo));
    return u;                      // [hi:lo]
}
__device__ __forceinline__ float bf_lo(uint32_t u) { return __uint_as_float(u << 16); }
__device__ __forceinline__ float bf_hi(uint32_t u) { return __uint_as_float(u & 0xFFFF0000u); }

// ---------------------------------------------------------------------------
// Kernel 0: segment boundaries, vectorized adjacent-diff scan.
// ---------------------------------------------------------------------------
__global__ void seg_bounds_scan(const int4* __restrict__ batch4,
                                const int*  __restrict__ batch, int N, int B)
{
    int t  = blockIdx.x * blockDim.x + threadIdx.x;
    int i  = t * 4;
    int nt = (N + 3) / 4;
    if (t > nt) return;
    if (t == nt) {
        int last = batch[N - 1];
        for (int v = last + 1; v <= B; v++) g_seg_start[v] = N;
        return;
    }
    int prev = (i == 0) ? -1 : batch[i - 1];
    if (i + 3 < N) {
        int4 c = batch4[t];
        int vals[4] = {c.x, c.y, c.z, c.w};
#pragma unroll
        for (int k = 0; k < 4; k++) {
            for (int v = prev + 1; v <= vals[k]; v++) g_seg_start[v] = i + k;
            prev = vals[k];
        }
    } else {
        for (int k = 0; k < 4 && i + k < N; k++) {
            int cur = batch[i + k];
            for (int v = prev + 1; v <= cur; v++) g_seg_start[v] = i + k;
            prev = cur;
        }
    }
}

// ---------------------------------------------------------------------------
// Kernel 1: per-segment attention pooling. One CTA per segment.
// R4 config (5 CTAs/SM) but cache stores rows as bf16: 160 rows in 40KB
// (2x the fp32 coverage). Pass 1 ascending: fp32 column sums (full precision),
// cached rows -> bf16 smem (loaded evict_first), uncached -> evict_last.
// Pass 2: cached rows from smem (bf16->f32 via shift), uncached from L2
// with evict_first.
// ---------------------------------------------------------------------------
__global__ void __launch_bounds__(NTHREADS)
attention_pool_kernel(const float4* __restrict__ x)
{
    __shared__ float4 s_partial[NWARPS][DV];       // 4KB
    __shared__ float4 s_coarse[DV];                // 512B
    __shared__ uint2  s_cache[CACHE_ROWS * 32];    // 40KB (bf16 rows)

    const int b     = blockIdx.x;
    const int start = g_seg_start[b];
    const int end   = g_seg_start[b + 1];
    const int cnt   = end - start;
    const float inv = 1.0f / (float)(cnt > 0 ? cnt : 1);
    const int w     = threadIdx.x >> 5;
    const int lane  = threadIdx.x & 31;

    const unsigned long long pol_last  = mk_policy_evict_last();
    const unsigned long long pol_first = mk_policy_evict_first();

    // ---- Pass 1: fp32 column sums; cache rows as bf16 ----
    float4 s = make_float4(0.f, 0.f, 0.f, 0.f);
    int r = start + w;
    for (; r + 3 * NWARPS < end; r += 4 * NWARPS) {
        float4 v[4];
#pragma unroll
        for (int k = 0; k < 4; k++) {
            int c = (r - start) + k * NWARPS;
            const float4* p = &x[(size_t)(r + k * NWARPS) * DV + lane];
            v[k] = ldg_hint(p, (c < CACHE_ROWS) ? pol_first : pol_last);
        }
#pragma unroll
        for (int k = 0; k < 4; k++) {
            int c = (r - start) + k * NWARPS;
            if (c < CACHE_ROWS) {
                uint2 u;
                u.x = pack_bf16x2(v[k].x, v[k].y);
                u.y = pack_bf16x2(v[k].z, v[k].w);
                s_cache[c * 32 + lane] = u;
            }
            s.x += v[k].x; s.y += v[k].y; s.z += v[k].z; s.w += v[k].w;
        }
    }
    for (; r < end; r += NWARPS) {
        int c = r - start;
        const float4* p = &x[(size_t)r * DV + lane];
        float4 v = ldg_hint(p, (c < CACHE_ROWS) ? pol_first : pol_last);
        if (c < CACHE_ROWS) {
            uint2 u;
            u.x = pack_bf16x2(v.x, v.y);
            u.y = pack_bf16x2(v.z, v.w);
            s_cache[c * 32 + lane] = u;
        }
        s.x += v.x; s.y += v.y; s.z += v.z; s.w += v.w;
    }
    s_partial[w][lane] = s;
    __syncthreads();
    if (threadIdx.x < 32) {
        float4 c = s_partial[0][lane];
#pragma unroll
        for (int i = 1; i < NWARPS; i++) {
            float4 t = s_partial[i][lane];
            c.x += t.x; c.y += t.y; c.z += t.z; c.w += t.w;
        }
        c.x *= inv; c.y *= inv; c.z *= inv; c.w *= inv;
        s_coarse[lane] = c;
    }
    __syncthreads();
    const float4 cf = s_coarse[lane];

    // ---- Pass 2a: cached rows (bf16 smem) ----
    float4 acc = make_float4(0.f, 0.f, 0.f, 0.f);
    {
        const int clim = (cnt < CACHE_ROWS) ? cnt : CACHE_ROWS;
        for (int c0 = w; c0 < clim; c0 += 2 * NWARPS) {
            int c1 = c0 + NWARPS;
            uint2 u0 = s_cache[c0 * 32 + lane];
            float4 v0 = make_float4(bf_lo(u0.x), bf_hi(u0.x), bf_lo(u0.y), bf_hi(u0.y));
            float d0 = v0.x * cf.x + v0.y * cf.y + v0.z * cf.z + v0.w * cf.w;
            float d1 = 0.f;
            float4 v1 = make_float4(0.f, 0.f, 0.f, 0.f);
            if (c1 < clim) {
                uint2 u1 = s_cache[c1 * 32 + lane];
                v1 = make_float4(bf_lo(u1.x), bf_hi(u1.x), bf_lo(u1.y), bf_hi(u1.y));
                d1 = v1.x * cf.x + v1.y * cf.y + v1.z * cf.z + v1.w * cf.w;
            }
#pragma unroll
            for (int o = 16; o > 0; o >>= 1) {
                d0 += __shfl_xor_sync(0xffffffffu, d0, o);
                d1 += __shfl_xor_sync(0xffffffffu, d1, o);
            }
            acc.x += v0.x * d0 + v1.x * d1;
            acc.y += v0.y * d0 + v1.y * d1;
            acc.z += v0.z * d0 + v1.z * d1;
            acc.w += v0.w * d0 + v1.w * d1;
        }
    }

    // ---- Pass 2b: uncached rows from L2 (evict_first) ----
    r = start + CACHE_ROWS + w;
    for (; r + NWARPS < end; r += 2 * NWARPS) {
        float4 v0 = ldg_hint(&x[(size_t)r * DV + lane], pol_first);
        float4 v1 = ldg_hint(&x[(size_t)(r + NWARPS) * DV + lane], pol_first);
        float d0 = v0.x * cf.x + v0.y * cf.y + v0.z * cf.z + v0.w * cf.w;
        float d1 = v1.x * cf.x + v1.y * cf.y + v1.z * cf.z + v1.w * cf.w;
#pragma unroll
        for (int o = 16; o > 0; o >>= 1) {
            d0 += __shfl_xor_sync(0xffffffffu, d0, o);
            d1 += __shfl_xor_sync(0xffffffffu, d1, o);
        }
        acc.x += v0.x * d0 + v1.x * d1;
        acc.y += v0.y * d0 + v1.y * d1;
        acc.z += v0.z * d0 + v1.z * d1;
        acc.w += v0.w * d0 + v1.w * d1;
    }
    if (r < end) {
        float4 v = ldg_hint(&x[(size_t)r * DV + lane], pol_first);
        float d = v.x * cf.x + v.y * cf.y + v.z * cf.z + v.w * cf.w;
#pragma unroll
        for (int o = 16; o > 0; o >>= 1)
            d += __shfl_xor_sync(0xffffffffu, d, o);
        acc.x += v.x * d; acc.y += v.y * d; acc.z += v.z * d; acc.w += v.w * d;
    }

    s_partial[w][lane] = acc;
    __syncthreads();
    if (threadIdx.x < 32) {
        float4 p = s_partial[0][lane];
#pragma unroll
        for (int i = 1; i < NWARPS; i++) {
            float4 t = s_partial[i][lane];
            p.x += t.x; p.y += t.y; p.z += t.z; p.w += t.w;
        }
        p.x *= inv; p.y *= inv; p.z *= inv; p.w *= inv;
        ((float4*)g_pooled)[(size_t)b * DV + lane] = p;
    }
}

// ---------------------------------------------------------------------------
// Kernel 2: out[B,128] = pooled[B,128] @ W^T + bias.
// ---------------------------------------------------------------------------
__global__ void __launch_bounds__(128)
out_gemm_kernel(const float* __restrict__ W, const float* __restrict__ bias,
                float* __restrict__ out, int B)
{
    __shared__ float sp[TR][D];   // 16KB
    const int rb = blockIdx.x * TR;
    int rows = B - rb; if (rows > TR) rows = TR;

    const float4* src = (const float4*)(g_pooled + (size_t)rb * D);
    float4* dst = (float4*)sp;
    for (int i = threadIdx.x; i < rows * DV; i += 128) dst[i] = src[i];
    __syncthreads();

    const int j = threadIdx.x;
    float acc[TR];
    const float bj = bias[j];
#pragma unroll
    for (int r2 = 0; r2 < TR; r2++) acc[r2] = bj;

    const float4* W4  = (const float4*)(W + (size_t)j * D);
    const float4* sp4 = (const float4*)sp;
    for (int k = 0; k < DV; k++) {
        float4 wv = W4[k];
#pragma unroll
        for (int r2 = 0; r2 < TR; r2++) {
            float4 pv = sp4[r2 * DV + k];
            acc[r2] += pv.x * wv.x + pv.y * wv.y + pv.z * wv.z + pv.w * wv.w;
        }
    }
    for (int r2 = 0; r2 < rows; r2++)
        out[(size_t)(rb + r2) * D + j] = acc[r2];
}

// ---------------------------------------------------------------------------
extern "C" void kernel_launch(void* const* d_in, const int* in_sizes, int n_in,
                              void* d_out, int out_size)
{
    const float* x     = (const float*)d_in[0];
    const int*   batch = (const int*)  d_in[1];
    const float* W     = (const float*)d_in[2];
    const float* bias  = (const float*)d_in[3];
    (void)n_in;

    const int N = in_sizes[1];
    const int B = out_size / D;

    int nt = (N + 3) / 4 + 1;
    seg_bounds_scan<<<(nt + 255) / 256, 256>>>((const int4*)batch, batch, N, B);
    attention_pool_kernel<<<B, NTHREADS>>>((const float4*)x);
    out_gemm_kernel<<<(B + TR - 1) / TR, 128>>>(W, bias, (float*)d_out, B);
}

// round 9
// speedup vs baseline: 1.1664x; 1.0006x over previous
#include <cuda_runtime.h>
#include <cuda_fp16.h>
#include <cstdint>

#define D          128
#define DV         (D / 4)      // 32 float4 per row
#define NWARPS     8
#define NTHREADS   256
#define CACHE_ROWS 160          // fp16 rows: 160 * 256B = 40KB smem cache
#define MAXB       16384
#define TR         32           // GEMM row tile

// Scratch (allocation-free per harness rules)
__device__ int   g_seg_start[MAXB + 1];
__device__ float g_pooled[(size_t)MAXB * D];

// ---- L2 eviction-policy hinted float4 loads ------------------------------
__device__ __forceinline__ unsigned long long mk_policy_evict_last() {
    unsigned long long p;
    asm("createpolicy.fractional.L2::evict_last.b64 %0, 1.0;" : "=l"(p));
    return p;
}
__device__ __forceinline__ unsigned long long mk_policy_evict_first() {
    unsigned long long p;
    asm("createpolicy.fractional.L2::evict_first.b64 %0, 1.0;" : "=l"(p));
    return p;
}
__device__ __forceinline__ float4 ldg_hint(const float4* p, unsigned long long pol) {
    float4 v;
    asm volatile("ld.global.nc.L2::cache_hint.v4.f32 {%0,%1,%2,%3}, [%4], %5;"
                 : "=f"(v.x), "=f"(v.y), "=f"(v.z), "=f"(v.w)
                 : "l"(p), "l"(pol));
    return v;
}

// ---- fp16x2 pack/unpack (10-bit mantissa: 8x less rounding than bf16) ----
__device__ __forceinline__ uint32_t pack_f16x2(float lo, float hi) {
    uint32_t u;
    asm("cvt.rn.f16x2.f32 %0, %1, %2;" : "=r"(u) : "f"(hi), "f"(lo));
    return u;                      // [hi:lo]
}
__device__ __forceinline__ float2 unpack_f16x2(uint32_t u) {
    return __half22float2(*reinterpret_cast<const __half2*>(&u));
}

// ---------------------------------------------------------------------------
// Kernel 0: segment boundaries, vectorized adjacent-diff scan.
// ---------------------------------------------------------------------------
__global__ void seg_bounds_scan(const int4* __restrict__ batch4,
                                const int*  __restrict__ batch, int N, int B)
{
    int t  = blockIdx.x * blockDim.x + threadIdx.x;
    int i  = t * 4;
    int nt = (N + 3) / 4;
    if (t > nt) return;
    if (t == nt) {
        int last = batch[N - 1];
        for (int v = last + 1; v <= B; v++) g_seg_start[v] = N;
        return;
    }
    int prev = (i == 0) ? -1 : batch[i - 1];
    if (i + 3 < N) {
        int4 c = batch4[t];
        int vals[4] = {c.x, c.y, c.z, c.w};
#pragma unroll
        for (int k = 0; k < 4; k++) {
            for (int v = prev + 1; v <= vals[k]; v++) g_seg_start[v] = i + k;
            prev = vals[k];
        }
    } else {
        for (int k = 0; k < 4 && i + k < N; k++) {
            int cur = batch[i + k];
            for (int v = prev + 1; v <= cur; v++) g_seg_start[v] = i + k;
            prev = cur;
        }
    }
}

// ---------------------------------------------------------------------------
// Kernel 1: per-segment attention pooling. One CTA per segment.
// 5 CTAs/SM config; cache stores rows as fp16: 160 rows in 40KB.
// Pass 1 ascending: fp32 column sums (full precision); cached rows -> fp16
// smem (loaded evict_first), uncached -> evict_last (survive to pass 2).
// Pass 2: cached rows from smem (fp16->f32), uncached from L2 evict_first.
// ---------------------------------------------------------------------------
__global__ void __launch_bounds__(NTHREADS)
attention_pool_kernel(const float4* __restrict__ x)
{
    __shared__ float4 s_partial[NWARPS][DV];       // 4KB
    __shared__ float4 s_coarse[DV];                // 512B
    __shared__ uint2  s_cache[CACHE_ROWS * 32];    // 40KB (fp16 rows)

    const int b     = blockIdx.x;
    const int start = g_seg_start[b];
    const int end   = g_seg_start[b + 1];
    const int cnt   = end - start;
    const float inv = 1.0f / (float)(cnt > 0 ? cnt : 1);
    const int w     = threadIdx.x >> 5;
    const int lane  = threadIdx.x & 31;

    const unsigned long long pol_last  = mk_policy_evict_last();
    const unsigned long long pol_first = mk_policy_evict_first();

    // ---- Pass 1: fp32 column sums; cache rows as fp16 ----
    float4 s = make_float4(0.f, 0.f, 0.f, 0.f);
    int r = start + w;
    for (; r + 3 * NWARPS < end; r += 4 * NWARPS) {
        float4 v[4];
#pragma unroll
        for (int k = 0; k < 4; k++) {
            int c = (r - start) + k * NWARPS;
            const float4* p = &x[(size_t)(r + k * NWARPS) * DV + lane];
            v[k] = ldg_hint(p, (c < CACHE_ROWS) ? pol_first : pol_last);
        }
#pragma unroll
        for (int k = 0; k < 4; k++) {
            int c = (r - start) + k * NWARPS;
            if (c < CACHE_ROWS) {
                uint2 u;
                u.x = pack_f16x2(v[k].x, v[k].y);
                u.y = pack_f16x2(v[k].z, v[k].w);
                s_cache[c * 32 + lane] = u;
            }
            s.x += v[k].x; s.y += v[k].y; s.z += v[k].z; s.w += v[k].w;
        }
    }
    for (; r < end; r += NWARPS) {
        int c = r - start;
        const float4* p = &x[(size_t)r * DV + lane];
        float4 v = ldg_hint(p, (c < CACHE_ROWS) ? pol_first : pol_last);
        if (c < CACHE_ROWS) {
            uint2 u;
            u.x = pack_f16x2(v.x, v.y);
            u.y = pack_f16x2(v.z, v.w);
            s_cache[c * 32 + lane] = u;
        }
        s.x += v.x; s.y += v.y; s.z += v.z; s.w += v.w;
    }
    s_partial[w][lane] = s;
    __syncthreads();
    if (threadIdx.x < 32) {
        float4 c = s_partial[0][lane];
#pragma unroll
        for (int i = 1; i < NWARPS; i++) {
            float4 t = s_partial[i][lane];
            c.x += t.x; c.y += t.y; c.z += t.z; c.w += t.w;
        }
        c.x *= inv; c.y *= inv; c.z *= inv; c.w *= inv;
        s_coarse[lane] = c;
    }
    __syncthreads();
    const float4 cf = s_coarse[lane];

    // ---- Pass 2a: cached rows (fp16 smem) ----
    float4 acc = make_float4(0.f, 0.f, 0.f, 0.f);
    {
        const int clim = (cnt < CACHE_ROWS) ? cnt : CACHE_ROWS;
        for (int c0 = w; c0 < clim; c0 += 2 * NWARPS) {
            int c1 = c0 + NWARPS;
            uint2 u0 = s_cache[c0 * 32 + lane];
            float2 a0 = unpack_f16x2(u0.x);
            float2 b0 = unpack_f16x2(u0.y);
            float4 v0 = make_float4(a0.x, a0.y, b0.x, b0.y);
            float d0 = v0.x * cf.x + v0.y * cf.y + v0.z * cf.z + v0.w * cf.w;
            float d1 = 0.f;
            float4 v1 = make_float4(0.f, 0.f, 0.f, 0.f);
            if (c1 < clim) {
                uint2 u1 = s_cache[c1 * 32 + lane];
                float2 a1 = unpack_f16x2(u1.x);
                float2 b1 = unpack_f16x2(u1.y);
                v1 = make_float4(a1.x, a1.y, b1.x, b1.y);
                d1 = v1.x * cf.x + v1.y * cf.y + v1.z * cf.z + v1.w * cf.w;
            }
#pragma unroll
            for (int o = 16; o > 0; o >>= 1) {
                d0 += __shfl_xor_sync(0xffffffffu, d0, o);
                d1 += __shfl_xor_sync(0xffffffffu, d1, o);
            }
            acc.x += v0.x * d0 + v1.x * d1;
            acc.y += v0.y * d0 + v1.y * d1;
            acc.z += v0.z * d0 + v1.z * d1;
            acc.w += v0.w * d0 + v1.w * d1;
        }
    }

    // ---- Pass 2b: uncached rows from L2 (evict_first) ----
    r = start + CACHE_ROWS + w;
    for (; r + NWARPS < end; r += 2 * NWARPS) {
        float4 v0 = ldg_hint(&x[(size_t)r * DV + lane], pol_first);
        float4 v1 = ldg_hint(&x[(size_t)(r + NWARPS) * DV + lane], pol_first);
        float d0 = v0.x * cf.x + v0.y * cf.y + v0.z * cf.z + v0.w * cf.w;
        float d1 = v1.x * cf.x + v1.y * cf.y + v1.z * cf.z + v1.w * cf.w;
#pragma unroll
        for (int o = 16; o > 0; o >>= 1) {
            d0 += __shfl_xor_sync(0xffffffffu, d0, o);
            d1 += __shfl_xor_sync(0xffffffffu, d1, o);
        }
        acc.x += v0.x * d0 + v1.x * d1;
        acc.y += v0.y * d0 + v1.y * d1;
        acc.z += v0.z * d0 + v1.z * d1;
        acc.w += v0.w * d0 + v1.w * d1;
    }
    if (r < end) {
        float4 v = ldg_hint(&x[(size_t)r * DV + lane], pol_first);
        float d = v.x * cf.x + v.y * cf.y + v.z * cf.z + v.w * cf.w;
#pragma unroll
        for (int o = 16; o > 0; o >>= 1)
            d += __shfl_xor_sync(0xffffffffu, d, o);
        acc.x += v.x * d; acc.y += v.y * d; acc.z += v.z * d; acc.w += v.w * d;
    }

    s_partial[w][lane] = acc;
    __syncthreads();
    if (threadIdx.x < 32) {
        float4 p = s_partial[0][lane];
#pragma unroll
        for (int i = 1; i < NWARPS; i++) {
            float4 t = s_partial[i][lane];
            p.x += t.x; p.y += t.y; p.z += t.z; p.w += t.w;
        }
        p.x *= inv; p.y *= inv; p.z *= inv; p.w *= inv;
        ((float4*)g_pooled)[(size_t)b * DV + lane] = p;
    }
}

// ---------------------------------------------------------------------------
// Kernel 2: out[B,128] = pooled[B,128] @ W^T + bias.
// ---------------------------------------------------------------------------
__global__ void __launch_bounds__(128)
out_gemm_kernel(const float* __restrict__ W, const float* __restrict__ bias,
                float* __restrict__ out, int B)
{
    __shared__ float sp[TR][D];   // 16KB
    const int rb = blockIdx.x * TR;
    int rows = B - rb; if (rows > TR) rows = TR;

    const float4* src = (const float4*)(g_pooled + (size_t)rb * D);
    float4* dst = (float4*)sp;
    for (int i = threadIdx.x; i < rows * DV; i += 128) dst[i] = src[i];
    __syncthreads();

    const int j = threadIdx.x;
    float acc[TR];
    const float bj = bias[j];
#pragma unroll
    for (int r2 = 0; r2 < TR; r2++) acc[r2] = bj;

    const float4* W4  = (const float4*)(W + (size_t)j * D);
    const float4* sp4 = (const float4*)sp;
    for (int k = 0; k < DV; k++) {
        float4 wv = W4[k];
#pragma unroll
        for (int r2 = 0; r2 < TR; r2++) {
            float4 pv = sp4[r2 * DV + k];
            acc[r2] += pv.x * wv.x + pv.y * wv.y + pv.z * wv.z + pv.w * wv.w;
        }
    }
    for (int r2 = 0; r2 < rows; r2++)
        out[(size_t)(rb + r2) * D + j] = acc[r2];
}

// ---------------------------------------------------------------------------
extern "C" void kernel_launch(void* const* d_in, const int* in_sizes, int n_in,
                              void* d_out, int out_size)
{
    const float* x     = (const float*)d_in[0];
    const int*   batch = (const int*)  d_in[1];
    const float* W     = (const float*)d_in[2];
    const float* bias  = (const float*)d_in[3];
    (void)n_in;

    const int N = in_sizes[1];
    const int B = out_size / D;

    int nt = (N + 3) / 4 + 1;
    seg_bounds_scan<<<(nt + 255) / 256, 256>>>((const int4*)batch, batch, N, B);
    attention_pool_kernel<<<B, NTHREADS>>>((const float4*)x);
    out_gemm_kernel<<<(B + TR - 1) / TR, 128>>>(W, bias, (float*)d_out, B);
}

// round 11
// speedup vs baseline: 1.2471x; 1.0692x over previous
#include <cuda_runtime.h>
#include <cuda_fp16.h>
#include <cstdint>

#define D          128
#define DV         (D / 4)      // 32 float4 per row
#define NWARPS     8
#define NTHREADS   256
#define CACHE_ROWS 160          // fp16 rows in smem: 160 * 256B = 40KB
#define RSLOTS     8            // reg-cached rows per warp slot (64 rows total)
#define REG_ROWS   (RSLOTS * NWARPS)
#define COVERED    (CACHE_ROWS + REG_ROWS)   // 224 rows cached on-chip
#define MAXB       16384
#define TR         32           // GEMM row tile

// Scratch (allocation-free per harness rules)
__device__ int   g_seg_start[MAXB + 1];
__device__ float g_pooled[(size_t)MAXB * D];

// ---- L2 eviction-policy hinted float4 loads ------------------------------
__device__ __forceinline__ unsigned long long mk_policy_evict_last() {
    unsigned long long p;
    asm("createpolicy.fractional.L2::evict_last.b64 %0, 1.0;" : "=l"(p));
    return p;
}
__device__ __forceinline__ unsigned long long mk_policy_evict_first() {
    unsigned long long p;
    asm("createpolicy.fractional.L2::evict_first.b64 %0, 1.0;" : "=l"(p));
    return p;
}
__device__ __forceinline__ float4 ldg_hint(const float4* p, unsigned long long pol) {
    float4 v;
    asm volatile("ld.global.nc.L2::cache_hint.v4.f32 {%0,%1,%2,%3}, [%4], %5;"
                 : "=f"(v.x), "=f"(v.y), "=f"(v.z), "=f"(v.w)
                 : "l"(p), "l"(pol));
    return v;
}

// ---- fp16x2 pack/unpack ----------------------------------------------------
__device__ __forceinline__ uint32_t pack_f16x2(float lo, float hi) {
    uint32_t u;
    asm("cvt.rn.f16x2.f32 %0, %1, %2;" : "=r"(u) : "f"(hi), "f"(lo));
    return u;
}
__device__ __forceinline__ float2 unpack_f16x2(uint32_t u) {
    return __half22float2(*reinterpret_cast<const __half2*>(&u));
}

// ---------------------------------------------------------------------------
// Kernel 0: segment boundaries, vectorized adjacent-diff scan.
// ---------------------------------------------------------------------------
__global__ void seg_bounds_scan(const int4* __restrict__ batch4,
                                const int*  __restrict__ batch, int N, int B)
{
    int t  = blockIdx.x * blockDim.x + threadIdx.x;
    int i  = t * 4;
    int nt = (N + 3) / 4;
    if (t > nt) return;
    if (t == nt) {
        int last = batch[N - 1];
        for (int v = last + 1; v <= B; v++) g_seg_start[v] = N;
        return;
    }
    int prev = (i == 0) ? -1 : batch[i - 1];
    if (i + 3 < N) {
        int4 c = batch4[t];
        int vals[4] = {c.x, c.y, c.z, c.w};
#pragma unroll
        for (int k = 0; k < 4; k++) {
            for (int v = prev + 1; v <= vals[k]; v++) g_seg_start[v] = i + k;
            prev = vals[k];
        }
    } else {
        for (int k = 0; k < 4 && i + k < N; k++) {
            int cur = batch[i + k];
            for (int v = prev + 1; v <= cur; v++) g_seg_start[v] = i + k;
            prev = cur;
        }
    }
}

// ---------------------------------------------------------------------------
// Kernel 1: per-segment attention pooling. One CTA per segment, 5 CTAs/SM.
// On-chip row cache (fp16): rows [0,160) in smem, rows [160,224) in regs
// (8 static slots/warp). ~92% of an avg 244-row segment never re-read.
// Pass 1: fp32 column sums; cached loads evict_first, stream loads evict_last.
// Pass 2: smem rows + reg rows + residual (L2, evict_first).
// ---------------------------------------------------------------------------
__global__ void __launch_bounds__(NTHREADS, 5)
attention_pool_kernel(const float4* __restrict__ x)
{
    __shared__ float4 s_partial[NWARPS][DV];       // 4KB
    __shared__ float4 s_coarse[DV];                // 512B
    __shared__ uint2  s_cache[CACHE_ROWS * 32];    // 40KB (fp16 rows)

    const int b     = blockIdx.x;
    const int start = g_seg_start[b];
    const int end   = g_seg_start[b + 1];
    const int cnt   = end - start;
    const float inv = 1.0f / (float)(cnt > 0 ? cnt : 1);
    const int w     = threadIdx.x >> 5;
    const int lane  = threadIdx.x & 31;

    const unsigned long long pol_last  = mk_policy_evict_last();
    const unsigned long long pol_first = mk_policy_evict_first();

    uint2 rc[RSLOTS];                              // register row cache (fp16)

    // ---- Pass 1a: smem-cached region [start, min(end, start+160)) ----
    float4 s = make_float4(0.f, 0.f, 0.f, 0.f);
    int lim1 = start + CACHE_ROWS; if (lim1 > end) lim1 = end;
    int r = start + w;
    for (; r + 3 * NWARPS < lim1; r += 4 * NWARPS) {
        float4 v[4];
#pragma unroll
        for (int k = 0; k < 4; k++)
            v[k] = ldg_hint(&x[(size_t)(r + k * NWARPS) * DV + lane], pol_first);
#pragma unroll
        for (int k = 0; k < 4; k++) {
            int c = (r - start) + k * NWARPS;
            uint2 u;
            u.x = pack_f16x2(v[k].x, v[k].y);
            u.y = pack_f16x2(v[k].z, v[k].w);
            s_cache[c * 32 + lane] = u;
            s.x += v[k].x; s.y += v[k].y; s.z += v[k].z; s.w += v[k].w;
        }
    }
    for (; r < lim1; r += NWARPS) {
        float4 v = ldg_hint(&x[(size_t)r * DV + lane], pol_first);
        int c = r - start;
        uint2 u;
        u.x = pack_f16x2(v.x, v.y);
        u.y = pack_f16x2(v.z, v.w);
        s_cache[c * 32 + lane] = u;
        s.x += v.x; s.y += v.y; s.z += v.z; s.w += v.w;
    }

    // ---- Pass 1b: reg-cached region [start+160, start+224) ----
#pragma unroll
    for (int jj = 0; jj < RSLOTS; jj++) {
        int rr = start + CACHE_ROWS + w + NWARPS * jj;
        rc[jj] = make_uint2(0u, 0u);
        if (rr < end) {
            float4 v = ldg_hint(&x[(size_t)rr * DV + lane], pol_first);
            rc[jj].x = pack_f16x2(v.x, v.y);
            rc[jj].y = pack_f16x2(v.z, v.w);
            s.x += v.x; s.y += v.y; s.z += v.z; s.w += v.w;
        }
    }

    // ---- Pass 1c: stream region [start+224, end) (evict_last) ----
    r = start + COVERED + w;
    for (; r + NWARPS < end; r += 2 * NWARPS) {
        float4 v0 = ldg_hint(&x[(size_t)r * DV + lane], pol_last);
        float4 v1 = ldg_hint(&x[(size_t)(r + NWARPS) * DV + lane], pol_last);
        s.x += v0.x + v1.x; s.y += v0.y + v1.y;
        s.z += v0.z + v1.z; s.w += v0.w + v1.w;
    }
    if (r < end) {
        float4 v = ldg_hint(&x[(size_t)r * DV + lane], pol_last);
        s.x += v.x; s.y += v.y; s.z += v.z; s.w += v.w;
    }

    s_partial[w][lane] = s;
    __syncthreads();
    if (threadIdx.x < 32) {
        float4 c = s_partial[0][lane];
#pragma unroll
        for (int i = 1; i < NWARPS; i++) {
            float4 t = s_partial[i][lane];
            c.x += t.x; c.y += t.y; c.z += t.z; c.w += t.w;
        }
        c.x *= inv; c.y *= inv; c.z *= inv; c.w *= inv;
        s_coarse[lane] = c;
    }
    __syncthreads();
    const float4 cf = s_coarse[lane];

    // ---- Pass 2a: smem-cached rows ----
    float4 acc = make_float4(0.f, 0.f, 0.f, 0.f);
    {
        const int clim = (cnt < CACHE_ROWS) ? cnt : CACHE_ROWS;
        for (int c0 = w; c0 < clim; c0 += 2 * NWARPS) {
            int c1 = c0 + NWARPS;
            uint2 u0 = s_cache[c0 * 32 + lane];
            float2 a0 = unpack_f16x2(u0.x);
            float2 b0 = unpack_f16x2(u0.y);
            float4 v0 = make_float4(a0.x, a0.y, b0.x, b0.y);
            float d0 = v0.x * cf.x + v0.y * cf.y + v0.z * cf.z + v0.w * cf.w;
            float d1 = 0.f;
            float4 v1 = make_float4(0.f, 0.f, 0.f, 0.f);
            if (c1 < clim) {
                uint2 u1 = s_cache[c1 * 32 + lane];
                float2 a1 = unpack_f16x2(u1.x);
                float2 b1 = unpack_f16x2(u1.y);
                v1 = make_float4(a1.x, a1.y, b1.x, b1.y);
                d1 = v1.x * cf.x + v1.y * cf.y + v1.z * cf.z + v1.w * cf.w;
            }
#pragma unroll
            for (int o = 16; o > 0; o >>= 1) {
                d0 += __shfl_xor_sync(0xffffffffu, d0, o);
                d1 += __shfl_xor_sync(0xffffffffu, d1, o);
            }
            acc.x += v0.x * d0 + v1.x * d1;
            acc.y += v0.y * d0 + v1.y * d1;
            acc.z += v0.z * d0 + v1.z * d1;
            acc.w += v0.w * d0 + v1.w * d1;
        }
    }

    // ---- Pass 2b: reg-cached rows ----
#pragma unroll
    for (int jj = 0; jj < RSLOTS; jj++) {
        int rr = start + CACHE_ROWS + w + NWARPS * jj;
        if (rr < end) {
            float2 a = unpack_f16x2(rc[jj].x);
            float2 bb = unpack_f16x2(rc[jj].y);
            float4 v = make_float4(a.x, a.y, bb.x, bb.y);
            float d = v.x * cf.x + v.y * cf.y + v.z * cf.z + v.w * cf.w;
#pragma unroll
            for (int o = 16; o > 0; o >>= 1)
                d += __shfl_xor_sync(0xffffffffu, d, o);
            acc.x += v.x * d; acc.y += v.y * d;
            acc.z += v.z * d; acc.w += v.w * d;
        }
    }

    // ---- Pass 2c: residual rows from L2 (evict_first) ----
    r = start + COVERED + w;
    for (; r + NWARPS < end; r += 2 * NWARPS) {
        float4 v0 = ldg_hint(&x[(size_t)r * DV + lane], pol_first);
        float4 v1 = ldg_hint(&x[(size_t)(r + NWARPS) * DV + lane], pol_first);
        float d0 = v0.x * cf.x + v0.y * cf.y + v0.z * cf.z + v0.w * cf.w;
        float d1 = v1.x * cf.x + v1.y * cf.y + v1.z * cf.z + v1.w * cf.w;
#pragma unroll
        for (int o = 16; o > 0; o >>= 1) {
            d0 += __shfl_xor_sync(0xffffffffu, d0, o);
            d1 += __shfl_xor_sync(0xffffffffu, d1, o);
        }
        acc.x += v0.x * d0 + v1.x * d1;
        acc.y += v0.y * d0 + v1.y * d1;
        acc.z += v0.z * d0 + v1.z * d1;
        acc.w += v0.w * d0 + v1.w * d1;
    }
    if (r < end) {
        float4 v = ldg_hint(&x[(size_t)r * DV + lane], pol_first);
        float d = v.x * cf.x + v.y * cf.y + v.z * cf.z + v.w * cf.w;
#pragma unroll
        for (int o = 16; o > 0; o >>= 1)
            d += __shfl_xor_sync(0xffffffffu, d, o);
        acc.x += v.x * d; acc.y += v.y * d; acc.z += v.z * d; acc.w += v.w * d;
    }

    s_partial[w][lane] = acc;
    __syncthreads();
    if (threadIdx.x < 32) {
        float4 p = s_partial[0][lane];
#pragma unroll
        for (int i = 1; i < NWARPS; i++) {
            float4 t = s_partial[i][lane];
            p.x += t.x; p.y += t.y; p.z += t.z; p.w += t.w;
        }
        p.x *= inv; p.y *= inv; p.z *= inv; p.w *= inv;
        ((float4*)g_pooled)[(size_t)b * DV + lane] = p;
    }
}

// ---------------------------------------------------------------------------
// Kernel 2: out[B,128] = pooled[B,128] @ W^T + bias.
// ---------------------------------------------------------------------------
__global__ void __launch_bounds__(128)
out_gemm_kernel(const float* __restrict__ W, const float* __restrict__ bias,
                float* __restrict__ out, int B)
{
    __shared__ float sp[TR][D];   // 16KB
    const int rb = blockIdx.x * TR;
    int rows = B - rb; if (rows > TR) rows = TR;

    const float4* src = (const float4*)(g_pooled + (size_t)rb * D);
    float4* dst = (float4*)sp;
    for (int i = threadIdx.x; i < rows * DV; i += 128) dst[i] = src[i];
    __syncthreads();

    const int j = threadIdx.x;
    float acc[TR];
    const float bj = bias[j];
#pragma unroll
    for (int r2 = 0; r2 < TR; r2++) acc[r2] = bj;

    const float4* W4  = (const float4*)(W + (size_t)j * D);
    const float4* sp4 = (const float4*)sp;
    for (int k = 0; k < DV; k++) {
        float4 wv = W4[k];
#pragma unroll
        for (int r2 = 0; r2 < TR; r2++) {
            float4 pv = sp4[r2 * DV + k];
            acc[r2] += pv.x * wv.x + pv.y * wv.y + pv.z * wv.z + pv.w * wv.w;
        }
    }
    for (int r2 = 0; r2 < rows; r2++)
        out[(size_t)(rb + r2) * D + j] = acc[r2];
}

// ---------------------------------------------------------------------------
extern "C" void kernel_launch(void* const* d_in, const int* in_sizes, int n_in,
                              void* d_out, int out_size)
{
    const float* x     = (const float*)d_in[0];
    const int*   batch = (const int*)  d_in[1];
    const float* W     = (const float*)d_in[2];
    const float* bias  = (const float*)d_in[3];
    (void)n_in;

    const int N = in_sizes[1];
    const int B = out_size / D;

    int nt = (N + 3) / 4 + 1;
    seg_bounds_scan<<<(nt + 255) / 256, 256>>>((const int4*)batch, batch, N, B);
    attention_pool_kernel<<<B, NTHREADS>>>((const float4*)x);
    out_gemm_kernel<<<(B + TR - 1) / TR, 128>>>(W, bias, (float*)d_out, B);
}